// round 2
// baseline (speedup 1.0000x reference)
#include <cuda_runtime.h>

#define NN 100000
#define NE 1600000

// Scratch (no cudaMalloc allowed): ~52 MB of device globals.
__device__ float g_deg[NN];
__device__ float g_dinv[NN];
__device__ __align__(16) float g_t[NN * 64];   // t1 = x@W1, later h = relu(agg1 + b1)
__device__ __align__(16) float g_a[NN * 64];   // agg accumulator (seeded with self-loop)

__global__ void k_deg_init() {
    int i = blockIdx.x * 256 + threadIdx.x;
    if (i < NN) g_deg[i] = 1.0f;   // self-loop contributes 1 to every in-degree
}

__global__ void k_degree(const int* __restrict__ dst) {
    int e = blockIdx.x * 256 + threadIdx.x;
    if (e < NE) atomicAdd(&g_deg[dst[e]], 1.0f);
}

__global__ void k_dinv() {
    int i = blockIdx.x * 256 + threadIdx.x;
    if (i < NN) g_dinv[i] = rsqrtf(g_deg[i]);
}

// t1 = x[N,128] @ W1[128,64]; also seed a = dinv^2 * t1 (self-loop message).
__global__ __launch_bounds__(256) void k_gemm1(const float* __restrict__ x,
                                               const float* __restrict__ W) {
    __shared__ float ws[128 * 64];    // 32 KB, full W1
    __shared__ float xs[16 * 132];    // 16-row x tile, padded vs bank conflicts
    const float4* W4 = (const float4*)W;
    float4* ws4 = (float4*)ws;
    #pragma unroll
    for (int i = threadIdx.x; i < 2048; i += 256) ws4[i] = W4[i];

    int row0 = blockIdx.x * 16;
    const float4* x4 = (const float4*)x;
    #pragma unroll
    for (int i = threadIdx.x; i < 512; i += 256) {
        int r = i >> 5, q = i & 31;
        int gr = row0 + r;
        float4 v = (gr < NN) ? x4[gr * 32 + q] : make_float4(0.f, 0.f, 0.f, 0.f);
        *(float4*)(xs + r * 132 + q * 4) = v;
    }
    __syncthreads();

    int tx = threadIdx.x & 15;   // output cols tx*4 .. tx*4+3
    int ty = threadIdx.x >> 4;   // output row within tile
    float4 acc = make_float4(0.f, 0.f, 0.f, 0.f);
    const float* xr = xs + ty * 132;
    #pragma unroll 8
    for (int k = 0; k < 128; k++) {
        float xv = xr[k];
        float4 w = ws4[k * 16 + tx];
        acc.x += xv * w.x; acc.y += xv * w.y;
        acc.z += xv * w.z; acc.w += xv * w.w;
    }
    int gr = row0 + ty;
    if (gr < NN) {
        ((float4*)g_t)[gr * 16 + tx] = acc;
        float s = g_dinv[gr];
        float s2 = s * s;
        ((float4*)g_a)[gr * 16 + tx] =
            make_float4(s2 * acc.x, s2 * acc.y, s2 * acc.z, s2 * acc.w);
    }
}

// Edge aggregation: a[dst] += dinv[src]*dinv[dst] * t[src], 64 floats/edge,
// 16 threads per edge, one float4 vector atomic each.
__global__ __launch_bounds__(256) void k_agg(const int* __restrict__ src,
                                             const int* __restrict__ dst) {
    int idx = blockIdx.x * 256 + threadIdx.x;
    int e = idx >> 4;
    if (e >= NE) return;
    int sub = idx & 15;
    int s = src[e];
    int d = dst[e];
    float n = g_dinv[s] * g_dinv[d];
    float4 v = ((const float4*)g_t)[s * 16 + sub];
    float4 m = make_float4(n * v.x, n * v.y, n * v.z, n * v.w);
    atomicAdd(((float4*)g_a) + d * 16 + sub, m);   // RED.E.ADD.F32 x4 (sm_90+)
}

// h = relu(a + b1) -> g_t ; reseed a = dinv^2 * h (self-loop for layer 2).
__global__ void k_relu_seed(const float* __restrict__ b1) {
    int i = blockIdx.x * 256 + threadIdx.x;
    if (i >= NN * 16) return;
    int node = i >> 4, c4 = i & 15;
    float4 v = ((float4*)g_a)[i];
    float4 b = ((const float4*)b1)[c4];
    v.x = fmaxf(v.x + b.x, 0.f);
    v.y = fmaxf(v.y + b.y, 0.f);
    v.z = fmaxf(v.z + b.z, 0.f);
    v.w = fmaxf(v.w + b.w, 0.f);
    ((float4*)g_t)[i] = v;
    float s = g_dinv[node];
    float s2 = s * s;
    v.x *= s2; v.y *= s2; v.z *= s2; v.w *= s2;
    ((float4*)g_a)[i] = v;
}

// out = a[N,64] @ W2[64,128] + b2
__global__ __launch_bounds__(256) void k_gemm2(const float* __restrict__ W2,
                                               const float* __restrict__ b2,
                                               float* __restrict__ out) {
    __shared__ float ws[64 * 128];   // 32 KB, full W2
    __shared__ float xs[16 * 65];    // 16-row a tile, padded
    const float4* W4 = (const float4*)W2;
    float4* ws4 = (float4*)ws;
    #pragma unroll
    for (int i = threadIdx.x; i < 2048; i += 256) ws4[i] = W4[i];

    int row0 = blockIdx.x * 16;
    const float4* a4 = (const float4*)g_a;
    {
        int i = threadIdx.x;            // exactly 256 float4 loads for the tile
        int r = i >> 4, q = i & 15;
        int gr = row0 + r;
        float4 v = (gr < NN) ? a4[gr * 16 + q] : make_float4(0.f, 0.f, 0.f, 0.f);
        float* p = xs + r * 65 + q * 4;
        p[0] = v.x; p[1] = v.y; p[2] = v.z; p[3] = v.w;
    }
    __syncthreads();

    int tx = threadIdx.x & 31;   // output cols tx*4 .. tx*4+3
    int ty = threadIdx.x >> 5;   // rows ty and ty+8
    float4 acc0 = make_float4(0.f, 0.f, 0.f, 0.f);
    float4 acc1 = make_float4(0.f, 0.f, 0.f, 0.f);
    const float* xr0 = xs + ty * 65;
    const float* xr1 = xs + (ty + 8) * 65;
    #pragma unroll 8
    for (int k = 0; k < 64; k++) {
        float4 w = ws4[k * 32 + tx];
        float x0 = xr0[k], x1 = xr1[k];
        acc0.x += x0 * w.x; acc0.y += x0 * w.y; acc0.z += x0 * w.z; acc0.w += x0 * w.w;
        acc1.x += x1 * w.x; acc1.y += x1 * w.y; acc1.z += x1 * w.z; acc1.w += x1 * w.w;
    }
    float4 b = ((const float4*)b2)[tx];
    acc0.x += b.x; acc0.y += b.y; acc0.z += b.z; acc0.w += b.w;
    acc1.x += b.x; acc1.y += b.y; acc1.z += b.z; acc1.w += b.w;
    int g0 = row0 + ty, g1 = row0 + ty + 8;
    if (g0 < NN) ((float4*)out)[g0 * 32 + tx] = acc0;
    if (g1 < NN) ((float4*)out)[g1 * 32 + tx] = acc1;
}

extern "C" void kernel_launch(void* const* d_in, const int* in_sizes, int n_in,
                              void* d_out, int out_size) {
    const float* x  = (const float*)d_in[0];
    const int*   ei = (const int*)d_in[1];   // [2, E] int32 (JAX x64 disabled)
    const float* W1 = (const float*)d_in[2];
    const float* b1 = (const float*)d_in[3];
    const float* W2 = (const float*)d_in[4];
    const float* b2 = (const float*)d_in[5];
    float* out = (float*)d_out;

    const int* src = ei;
    const int* dst = ei + NE;

    k_deg_init <<<(NN + 255) / 256, 256>>>();
    k_degree   <<<(NE + 255) / 256, 256>>>(dst);
    k_dinv     <<<(NN + 255) / 256, 256>>>();
    k_gemm1    <<<NN / 16, 256>>>(x, W1);            // 6250 blocks (exact)
    k_agg      <<<(NE * 16) / 256, 256>>>(src, dst); // layer-1 aggregation
    k_relu_seed<<<(NN * 16) / 256, 256>>>(b1);
    k_agg      <<<(NE * 16) / 256, 256>>>(src, dst); // layer-2 aggregation (64-wide)
    k_gemm2    <<<NN / 16, 256>>>(W2, b2, out);
}

// round 4
// speedup vs baseline: 1.3456x; 1.3456x over previous
#include <cuda_runtime.h>

#define NN 100000
#define NE 1600000

__device__ float g_deg[NN];
__device__ float g_dinv[NN];
__device__ __align__(16) float g_t[NN * 64];   // tt = dinv*(x@W1), later hh = dinv*h
__device__ __align__(16) float g_a[NN * 64];   // agg accumulator (seeded with self term)

__global__ void k_deg_init() {
    int i = blockIdx.x * 256 + threadIdx.x;
    if (i < NN) g_deg[i] = 1.0f;
}

__global__ void k_degree(const int* __restrict__ dst) {
    int e = blockIdx.x * 256 + threadIdx.x;
    if (e < NE) atomicAdd(&g_deg[dst[e]], 1.0f);
}

__global__ void k_dinv() {
    int i = blockIdx.x * 256 + threadIdx.x;
    if (i < NN) g_dinv[i] = rsqrtf(g_deg[i]);
}

// t1 = x[N,128] @ W1[128,64]; store tt = dinv*t1 into BOTH g_t (gather source)
// and g_a (self-loop seed). 64-row tiles, k-chunked (2x64), 4x4 register blocking.
__global__ __launch_bounds__(256) void k_gemm1(const float* __restrict__ x,
                                               const float* __restrict__ W) {
    __shared__ float ws[64 * 64];     // W k-chunk [kk][col], 16 KB
    __shared__ float xsT[64 * 68];    // x tile transposed [kk][row], padded, 17.4 KB
    int row0 = blockIdx.x * 64;
    int tx = threadIdx.x & 15;        // cols 4tx..4tx+3
    int ty = threadIdx.x >> 4;        // rows 4ty..4ty+3
    float4 acc0 = {0,0,0,0}, acc1 = {0,0,0,0}, acc2 = {0,0,0,0}, acc3 = {0,0,0,0};
    const float4* x4 = (const float4*)x;
    const float4* W4 = (const float4*)W;

    #pragma unroll
    for (int c = 0; c < 2; c++) {
        __syncthreads();
        #pragma unroll
        for (int i = threadIdx.x; i < 1024; i += 256)
            ((float4*)ws)[i] = W4[c * 1024 + i];      // W1 rows 64c..64c+63
        #pragma unroll
        for (int i = threadIdx.x; i < 1024; i += 256) {
            int r = i & 63, q = i >> 6;               // q: float4 index in k-chunk
            int gr = row0 + r;
            float4 v = (gr < NN) ? x4[gr * 32 + c * 16 + q] : make_float4(0,0,0,0);
            int kk = q * 4;
            xsT[(kk + 0) * 68 + r] = v.x;
            xsT[(kk + 1) * 68 + r] = v.y;
            xsT[(kk + 2) * 68 + r] = v.z;
            xsT[(kk + 3) * 68 + r] = v.w;
        }
        __syncthreads();
        #pragma unroll 16
        for (int kk = 0; kk < 64; kk++) {
            float4 xv = *(const float4*)&xsT[kk * 68 + ty * 4];
            float4 w  = ((const float4*)ws)[kk * 16 + tx];
            acc0.x += xv.x*w.x; acc0.y += xv.x*w.y; acc0.z += xv.x*w.z; acc0.w += xv.x*w.w;
            acc1.x += xv.y*w.x; acc1.y += xv.y*w.y; acc1.z += xv.y*w.z; acc1.w += xv.y*w.w;
            acc2.x += xv.z*w.x; acc2.y += xv.z*w.y; acc2.z += xv.z*w.z; acc2.w += xv.z*w.w;
            acc3.x += xv.w*w.x; acc3.y += xv.w*w.y; acc3.z += xv.w*w.z; acc3.w += xv.w*w.w;
        }
    }
    float4 accs[4] = {acc0, acc1, acc2, acc3};
    #pragma unroll
    for (int j = 0; j < 4; j++) {
        int gr = row0 + ty * 4 + j;
        if (gr < NN) {
            float s = g_dinv[gr];
            float4 v = accs[j];
            v.x *= s; v.y *= s; v.z *= s; v.w *= s;
            ((float4*)g_t)[gr * 16 + tx] = v;
            ((float4*)g_a)[gr * 16 + tx] = v;
        }
    }
}

// Pure gather + vector scatter-add: a[dst] += tt[src] (norm hoisted out).
__global__ __launch_bounds__(256) void k_agg(const int* __restrict__ src,
                                             const int* __restrict__ dst) {
    int idx = blockIdx.x * 256 + threadIdx.x;
    int e = idx >> 4;
    if (e >= NE) return;
    int sub = idx & 15;
    int s = src[e];
    int d = dst[e];
    float4 v = ((const float4*)g_t)[s * 16 + sub];
    atomicAdd(((float4*)g_a) + d * 16 + sub, v);
}

// h = relu(dinv*a + b1); store hh = dinv*h into g_t and reseed g_a = hh.
__global__ void k_relu_seed(const float* __restrict__ b1) {
    int i = blockIdx.x * 256 + threadIdx.x;
    if (i >= NN * 16) return;
    int node = i >> 4, c4 = i & 15;
    float s = g_dinv[node];
    float4 v = ((float4*)g_a)[i];
    float4 b = ((const float4*)b1)[c4];
    v.x = fmaxf(s * v.x + b.x, 0.f);
    v.y = fmaxf(s * v.y + b.y, 0.f);
    v.z = fmaxf(s * v.z + b.z, 0.f);
    v.w = fmaxf(s * v.w + b.w, 0.f);
    v.x *= s; v.y *= s; v.z *= s; v.w *= s;
    ((float4*)g_t)[i] = v;
    ((float4*)g_a)[i] = v;
}

// out = (dinv * a)[N,64] @ W2[64,128] + b2. 32-row tiles, 4x4 blocking, static smem.
__global__ __launch_bounds__(256) void k_gemm2(const float* __restrict__ W2,
                                               const float* __restrict__ b2,
                                               float* __restrict__ out) {
    __shared__ float ws[64 * 128];    // full W2, 32 KB
    __shared__ float xsT[64 * 36];    // a tile transposed [k][row], padded, 9.2 KB
    const float4* W4 = (const float4*)W2;
    #pragma unroll
    for (int i = threadIdx.x; i < 2048; i += 256)
        ((float4*)ws)[i] = W4[i];

    int row0 = blockIdx.x * 32;
    const float4* a4 = (const float4*)g_a;
    #pragma unroll
    for (int i = threadIdx.x; i < 512; i += 256) {
        int r = i & 31, q = i >> 5;
        int gr = row0 + r;
        float4 v = make_float4(0,0,0,0);
        if (gr < NN) {
            v = a4[gr * 16 + q];
            float s = g_dinv[gr];
            v.x *= s; v.y *= s; v.z *= s; v.w *= s;
        }
        int k = q * 4;
        xsT[(k + 0) * 36 + r] = v.x;
        xsT[(k + 1) * 36 + r] = v.y;
        xsT[(k + 2) * 36 + r] = v.z;
        xsT[(k + 3) * 36 + r] = v.w;
    }
    __syncthreads();

    int tx = threadIdx.x & 31;        // cols 4tx..4tx+3
    int ty = threadIdx.x >> 5;        // rows 4ty..4ty+3 (ty 0..7)
    float4 acc0 = {0,0,0,0}, acc1 = {0,0,0,0}, acc2 = {0,0,0,0}, acc3 = {0,0,0,0};
    #pragma unroll 16
    for (int k = 0; k < 64; k++) {
        float4 xv = *(const float4*)&xsT[k * 36 + ty * 4];
        float4 w  = ((const float4*)ws)[k * 32 + tx];
        acc0.x += xv.x*w.x; acc0.y += xv.x*w.y; acc0.z += xv.x*w.z; acc0.w += xv.x*w.w;
        acc1.x += xv.y*w.x; acc1.y += xv.y*w.y; acc1.z += xv.y*w.z; acc1.w += xv.y*w.w;
        acc2.x += xv.z*w.x; acc2.y += xv.z*w.y; acc2.z += xv.z*w.z; acc2.w += xv.z*w.w;
        acc3.x += xv.w*w.x; acc3.y += xv.w*w.y; acc3.z += xv.w*w.z; acc3.w += xv.w*w.w;
    }
    float4 b = ((const float4*)b2)[tx];
    float4 accs[4] = {acc0, acc1, acc2, acc3};
    #pragma unroll
    for (int j = 0; j < 4; j++) {
        int gr = row0 + ty * 4 + j;
        if (gr < NN) {
            float4 v = accs[j];
            v.x += b.x; v.y += b.y; v.z += b.z; v.w += b.w;
            ((float4*)out)[gr * 32 + tx] = v;
        }
    }
}

extern "C" void kernel_launch(void* const* d_in, const int* in_sizes, int n_in,
                              void* d_out, int out_size) {
    const float* x  = (const float*)d_in[0];
    const int*   ei = (const int*)d_in[1];   // [2, E] int32
    const float* W1 = (const float*)d_in[2];
    const float* b1 = (const float*)d_in[3];
    const float* W2 = (const float*)d_in[4];
    const float* b2 = (const float*)d_in[5];
    float* out = (float*)d_out;

    const int* src = ei;
    const int* dst = ei + NE;

    k_deg_init <<<(NN + 255) / 256, 256>>>();
    k_degree   <<<(NE + 255) / 256, 256>>>(dst);
    k_dinv     <<<(NN + 255) / 256, 256>>>();
    k_gemm1    <<<(NN + 63) / 64, 256>>>(x, W1);
    k_agg      <<<(NE * 16) / 256, 256>>>(src, dst);   // layer-1 aggregation
    k_relu_seed<<<(NN * 16) / 256, 256>>>(b1);
    k_agg      <<<(NE * 16) / 256, 256>>>(src, dst);   // layer-2 aggregation
    k_gemm2    <<<(NN + 31) / 32, 256>>>(W2, b2, out);
}

// round 5
// speedup vs baseline: 1.8664x; 1.3870x over previous
#include <cuda_runtime.h>

#define NN 100000
#define NE 1600000
#define NB_SCAN ((NN + 1023) / 1024)   // 98

__device__ int   g_cnt[NN];
__device__ int   g_off[NN + 1];
__device__ int   g_bsum[NB_SCAN];
__device__ int   g_fill[NN];
__device__ int   g_srcs[NE];
__device__ float g_dinv[NN];
__device__ __align__(16) float g_t[NN * 64];   // tt = dinv*(x@W1), later hh = dinv*relu(...)
__device__ __align__(16) float g_a[NN * 64];   // aggregation result

__global__ void k_zero() {
    int i = blockIdx.x * 256 + threadIdx.x;
    if (i < NN) g_cnt[i] = 0;
}

__global__ void k_count(const int* __restrict__ dst) {
    int e = blockIdx.x * 256 + threadIdx.x;
    if (e < NE) atomicAdd(&g_cnt[dst[e]], 1);
}

__global__ void k_dinv() {
    int i = blockIdx.x * 256 + threadIdx.x;
    if (i < NN) g_dinv[i] = rsqrtf((float)(g_cnt[i] + 1));   // +1 self-loop
}

// ---- 3-kernel exclusive prefix scan of g_cnt into g_off ----
__global__ __launch_bounds__(256) void k_scan1() {
    __shared__ int sh[256];
    int b = blockIdx.x, t = threadIdx.x;
    int base = b * 1024 + t * 4;
    int c0 = (base + 0 < NN) ? g_cnt[base + 0] : 0;
    int c1 = (base + 1 < NN) ? g_cnt[base + 1] : 0;
    int c2 = (base + 2 < NN) ? g_cnt[base + 2] : 0;
    int c3 = (base + 3 < NN) ? g_cnt[base + 3] : 0;
    int s = c0 + c1 + c2 + c3;
    sh[t] = s;
    __syncthreads();
    for (int ofs = 1; ofs < 256; ofs <<= 1) {
        int v = (t >= ofs) ? sh[t - ofs] : 0;
        __syncthreads();
        sh[t] += v;
        __syncthreads();
    }
    int excl = sh[t] - s;   // block-local exclusive prefix
    if (base + 0 < NN) g_off[base + 0] = excl;
    if (base + 1 < NN) g_off[base + 1] = excl + c0;
    if (base + 2 < NN) g_off[base + 2] = excl + c0 + c1;
    if (base + 3 < NN) g_off[base + 3] = excl + c0 + c1 + c2;
    if (t == 255) g_bsum[b] = sh[255];
}

__global__ void k_scan2() {
    if (threadIdx.x == 0) {
        int run = 0;
        for (int b = 0; b < NB_SCAN; b++) { int v = g_bsum[b]; g_bsum[b] = run; run += v; }
        g_off[NN] = run;   // == NE
    }
}

__global__ void k_scan3() {
    int i = blockIdx.x * 256 + threadIdx.x;
    if (i < NN) {
        g_off[i] += g_bsum[i >> 10];
        g_fill[i] = 0;
    }
}

__global__ void k_fillcsr(const int* __restrict__ src, const int* __restrict__ dst) {
    int e = blockIdx.x * 256 + threadIdx.x;
    if (e < NE) {
        int d = dst[e];
        int pos = g_off[d] + atomicAdd(&g_fill[d], 1);
        g_srcs[pos] = src[e];
    }
}

// t1 = x[N,128] @ W1[128,64]; store tt = dinv*t1 into g_t.
__global__ __launch_bounds__(256) void k_gemm1(const float* __restrict__ x,
                                               const float* __restrict__ W) {
    __shared__ float ws[64 * 64];     // W k-chunk [kk][col]
    __shared__ float xsT[64 * 68];    // x tile transposed [kk][row], padded
    int row0 = blockIdx.x * 64;
    int tx = threadIdx.x & 15;        // cols 4tx..4tx+3
    int ty = threadIdx.x >> 4;        // rows 4ty..4ty+3
    float4 acc0 = {0,0,0,0}, acc1 = {0,0,0,0}, acc2 = {0,0,0,0}, acc3 = {0,0,0,0};
    const float4* x4 = (const float4*)x;
    const float4* W4 = (const float4*)W;

    #pragma unroll
    for (int c = 0; c < 2; c++) {
        __syncthreads();
        #pragma unroll
        for (int i = threadIdx.x; i < 1024; i += 256)
            ((float4*)ws)[i] = W4[c * 1024 + i];
        #pragma unroll
        for (int i = threadIdx.x; i < 1024; i += 256) {
            int r = i & 63, q = i >> 6;
            int gr = row0 + r;
            float4 v = (gr < NN) ? x4[gr * 32 + c * 16 + q] : make_float4(0,0,0,0);
            int kk = q * 4;
            xsT[(kk + 0) * 68 + r] = v.x;
            xsT[(kk + 1) * 68 + r] = v.y;
            xsT[(kk + 2) * 68 + r] = v.z;
            xsT[(kk + 3) * 68 + r] = v.w;
        }
        __syncthreads();
        #pragma unroll 16
        for (int kk = 0; kk < 64; kk++) {
            float4 xv = *(const float4*)&xsT[kk * 68 + ty * 4];
            float4 w  = ((const float4*)ws)[kk * 16 + tx];
            acc0.x += xv.x*w.x; acc0.y += xv.x*w.y; acc0.z += xv.x*w.z; acc0.w += xv.x*w.w;
            acc1.x += xv.y*w.x; acc1.y += xv.y*w.y; acc1.z += xv.y*w.z; acc1.w += xv.y*w.w;
            acc2.x += xv.z*w.x; acc2.y += xv.z*w.y; acc2.z += xv.z*w.z; acc2.w += xv.z*w.w;
            acc3.x += xv.w*w.x; acc3.y += xv.w*w.y; acc3.z += xv.w*w.z; acc3.w += xv.w*w.w;
        }
    }
    float4 accs[4] = {acc0, acc1, acc2, acc3};
    #pragma unroll
    for (int j = 0; j < 4; j++) {
        int gr = row0 + ty * 4 + j;
        if (gr < NN) {
            float s = g_dinv[gr];
            float4 v = accs[j];
            v.x *= s; v.y *= s; v.z *= s; v.w *= s;
            ((float4*)g_t)[gr * 16 + tx] = v;
        }
    }
}

// CSR gather-reduce: a[d] = tt[d] + sum_{s in nbrs(d)} tt[s]. No atomics.
// 16 threads per node, 2-way unrolled gather for MLP.
__global__ __launch_bounds__(256) void k_aggcsr() {
    int idx = blockIdx.x * 256 + threadIdx.x;
    int d = idx >> 4;
    if (d >= NN) return;
    int sub = idx & 15;
    const float4* t4 = (const float4*)g_t;
    int beg = g_off[d], end = g_off[d + 1];
    float4 acc0 = t4[d * 16 + sub];   // self-loop term
    float4 acc1 = {0, 0, 0, 0};
    int j = beg;
    for (; j + 1 < end; j += 2) {
        int s0 = g_srcs[j];
        int s1 = g_srcs[j + 1];
        float4 v0 = t4[s0 * 16 + sub];
        float4 v1 = t4[s1 * 16 + sub];
        acc0.x += v0.x; acc0.y += v0.y; acc0.z += v0.z; acc0.w += v0.w;
        acc1.x += v1.x; acc1.y += v1.y; acc1.z += v1.z; acc1.w += v1.w;
    }
    if (j < end) {
        int s0 = g_srcs[j];
        float4 v0 = t4[s0 * 16 + sub];
        acc0.x += v0.x; acc0.y += v0.y; acc0.z += v0.z; acc0.w += v0.w;
    }
    acc0.x += acc1.x; acc0.y += acc1.y; acc0.z += acc1.z; acc0.w += acc1.w;
    ((float4*)g_a)[d * 16 + sub] = acc0;
}

// h = relu(dinv*a + b1); store hh = dinv*h into g_t.
__global__ void k_relu(const float* __restrict__ b1) {
    int i = blockIdx.x * 256 + threadIdx.x;
    if (i >= NN * 16) return;
    int node = i >> 4, c4 = i & 15;
    float s = g_dinv[node];
    float4 v = ((float4*)g_a)[i];
    float4 b = ((const float4*)b1)[c4];
    v.x = fmaxf(s * v.x + b.x, 0.f) * s;
    v.y = fmaxf(s * v.y + b.y, 0.f) * s;
    v.z = fmaxf(s * v.z + b.z, 0.f) * s;
    v.w = fmaxf(s * v.w + b.w, 0.f) * s;
    ((float4*)g_t)[i] = v;
}

// out = (dinv * a)[N,64] @ W2[64,128] + b2.
__global__ __launch_bounds__(256) void k_gemm2(const float* __restrict__ W2,
                                               const float* __restrict__ b2,
                                               float* __restrict__ out) {
    __shared__ float ws[64 * 128];
    __shared__ float xsT[64 * 36];
    const float4* W4 = (const float4*)W2;
    #pragma unroll
    for (int i = threadIdx.x; i < 2048; i += 256)
        ((float4*)ws)[i] = W4[i];

    int row0 = blockIdx.x * 32;
    const float4* a4 = (const float4*)g_a;
    #pragma unroll
    for (int i = threadIdx.x; i < 512; i += 256) {
        int r = i & 31, q = i >> 5;
        int gr = row0 + r;
        float4 v = make_float4(0,0,0,0);
        if (gr < NN) {
            v = a4[gr * 16 + q];
            float s = g_dinv[gr];
            v.x *= s; v.y *= s; v.z *= s; v.w *= s;
        }
        int k = q * 4;
        xsT[(k + 0) * 36 + r] = v.x;
        xsT[(k + 1) * 36 + r] = v.y;
        xsT[(k + 2) * 36 + r] = v.z;
        xsT[(k + 3) * 36 + r] = v.w;
    }
    __syncthreads();

    int tx = threadIdx.x & 31;
    int ty = threadIdx.x >> 5;
    float4 acc0 = {0,0,0,0}, acc1 = {0,0,0,0}, acc2 = {0,0,0,0}, acc3 = {0,0,0,0};
    #pragma unroll 16
    for (int k = 0; k < 64; k++) {
        float4 xv = *(const float4*)&xsT[k * 36 + ty * 4];
        float4 w  = ((const float4*)ws)[k * 32 + tx];
        acc0.x += xv.x*w.x; acc0.y += xv.x*w.y; acc0.z += xv.x*w.z; acc0.w += xv.x*w.w;
        acc1.x += xv.y*w.x; acc1.y += xv.y*w.y; acc1.z += xv.y*w.z; acc1.w += xv.y*w.w;
        acc2.x += xv.z*w.x; acc2.y += xv.z*w.y; acc2.z += xv.z*w.z; acc2.w += xv.z*w.w;
        acc3.x += xv.w*w.x; acc3.y += xv.w*w.y; acc3.z += xv.w*w.z; acc3.w += xv.w*w.w;
    }
    float4 b = ((const float4*)b2)[tx];
    float4 accs[4] = {acc0, acc1, acc2, acc3};
    #pragma unroll
    for (int j = 0; j < 4; j++) {
        int gr = row0 + ty * 4 + j;
        if (gr < NN) {
            float4 v = accs[j];
            v.x += b.x; v.y += b.y; v.z += b.z; v.w += b.w;
            ((float4*)out)[gr * 32 + tx] = v;
        }
    }
}

extern "C" void kernel_launch(void* const* d_in, const int* in_sizes, int n_in,
                              void* d_out, int out_size) {
    const float* x  = (const float*)d_in[0];
    const int*   ei = (const int*)d_in[1];   // [2, E] int32
    const float* W1 = (const float*)d_in[2];
    const float* b1 = (const float*)d_in[3];
    const float* W2 = (const float*)d_in[4];
    const float* b2 = (const float*)d_in[5];
    float* out = (float*)d_out;

    const int* src = ei;
    const int* dst = ei + NE;

    // CSR build
    k_zero   <<<(NN + 255) / 256, 256>>>();
    k_count  <<<(NE + 255) / 256, 256>>>(dst);
    k_dinv   <<<(NN + 255) / 256, 256>>>();
    k_scan1  <<<NB_SCAN, 256>>>();
    k_scan2  <<<1, 32>>>();
    k_scan3  <<<(NN + 255) / 256, 256>>>();
    k_fillcsr<<<(NE + 255) / 256, 256>>>(src, dst);
    // GCN layers
    k_gemm1  <<<(NN + 63) / 64, 256>>>(x, W1);
    k_aggcsr <<<(NN * 16 + 255) / 256, 256>>>();        // layer-1 agg (no atomics)
    k_relu   <<<(NN * 16) / 256, 256>>>(b1);
    k_aggcsr <<<(NN * 16 + 255) / 256, 256>>>();        // layer-2 agg
    k_gemm2  <<<(NN + 31) / 32, 256>>>(W2, b2, out);
}

// round 6
// speedup vs baseline: 2.4959x; 1.3373x over previous
#include <cuda_runtime.h>

#define NN 100000
#define NE 1600000
#define NB_SCAN ((NN + 1023) / 1024)   // 98

__device__ int   g_cnt[NN];
__device__ int   g_off[NN + 1];
__device__ int   g_bsum[NB_SCAN];
__device__ int   g_fill[NN];
__device__ int   g_srcs[NE];
__device__ float g_dinv[NN];
__device__ __align__(16) float g_t[NN * 64];   // tt = dinv*(x@W1), later hh = dinv*relu(...)
__device__ __align__(16) float g_a[NN * 64];   // aggregation result

__device__ __forceinline__ unsigned f2tf(float f) {
    unsigned u;
    asm("cvt.rna.tf32.f32 %0, %1;" : "=r"(u) : "f"(f));
    return u;
}

__device__ __forceinline__ void mma_tf32(float* d, const unsigned* a, unsigned b0, unsigned b1) {
    asm("mma.sync.aligned.m16n8k8.row.col.f32.tf32.tf32.f32 "
        "{%0,%1,%2,%3},{%4,%5,%6,%7},{%8,%9},{%0,%1,%2,%3};"
        : "+f"(d[0]), "+f"(d[1]), "+f"(d[2]), "+f"(d[3])
        : "r"(a[0]), "r"(a[1]), "r"(a[2]), "r"(a[3]), "r"(b0), "r"(b1));
}

__global__ void k_zero() {
    int i = blockIdx.x * 256 + threadIdx.x;
    if (i < NN) g_cnt[i] = 0;
}

__global__ void k_count(const int* __restrict__ dst) {
    int e = blockIdx.x * 256 + threadIdx.x;
    if (e < NE) atomicAdd(&g_cnt[dst[e]], 1);
}

// ---- 3-kernel exclusive prefix scan of g_cnt into g_off ----
__global__ __launch_bounds__(256) void k_scan1() {
    __shared__ int sh[256];
    int b = blockIdx.x, t = threadIdx.x;
    int base = b * 1024 + t * 4;
    int c0 = (base + 0 < NN) ? g_cnt[base + 0] : 0;
    int c1 = (base + 1 < NN) ? g_cnt[base + 1] : 0;
    int c2 = (base + 2 < NN) ? g_cnt[base + 2] : 0;
    int c3 = (base + 3 < NN) ? g_cnt[base + 3] : 0;
    int s = c0 + c1 + c2 + c3;
    sh[t] = s;
    __syncthreads();
    for (int ofs = 1; ofs < 256; ofs <<= 1) {
        int v = (t >= ofs) ? sh[t - ofs] : 0;
        __syncthreads();
        sh[t] += v;
        __syncthreads();
    }
    int excl = sh[t] - s;
    if (base + 0 < NN) g_off[base + 0] = excl;
    if (base + 1 < NN) g_off[base + 1] = excl + c0;
    if (base + 2 < NN) g_off[base + 2] = excl + c0 + c1;
    if (base + 3 < NN) g_off[base + 3] = excl + c0 + c1 + c2;
    if (t == 255) g_bsum[b] = sh[255];
}

__global__ void k_scan2() {
    if (threadIdx.x == 0) {
        int run = 0;
        for (int b = 0; b < NB_SCAN; b++) { int v = g_bsum[b]; g_bsum[b] = run; run += v; }
        g_off[NN] = run;
    }
}

__global__ void k_scan3() {   // also computes dinv and zeroes fill counters
    int i = blockIdx.x * 256 + threadIdx.x;
    if (i < NN) {
        g_off[i] += g_bsum[i >> 10];
        g_fill[i] = 0;
        g_dinv[i] = rsqrtf((float)(g_cnt[i] + 1));
    }
}

__global__ void k_fillcsr(const int* __restrict__ src, const int* __restrict__ dst) {
    int e = blockIdx.x * 256 + threadIdx.x;
    if (e < NE) {
        int d = dst[e];
        int pos = g_off[d] + atomicAdd(&g_fill[d], 1);
        g_srcs[pos] = src[e];
    }
}

// tt = dinv * (x[N,128] @ W1[128,64]) via tf32 mma. 128 rows/block, 8 warps x 16 rows.
__global__ __launch_bounds__(256) void k_gemm1(const float* __restrict__ x,
                                               const float* __restrict__ W) {
    __shared__ unsigned xs[128 * 132];   // x tile, tf32, [row][k] pad 132
    __shared__ unsigned ws[128 * 72];    // W1, tf32, [k][n] pad 72
    int tid = threadIdx.x;
    int row0 = blockIdx.x * 128;
    const float4* x4 = (const float4*)x;
    const float4* W4 = (const float4*)W;

    #pragma unroll
    for (int i = tid; i < 2048; i += 256) {      // W1: 128x64 = 2048 float4
        int k = i >> 4, q = i & 15;
        float4 v = W4[i];
        unsigned* p = &ws[k * 72 + q * 4];
        p[0] = f2tf(v.x); p[1] = f2tf(v.y); p[2] = f2tf(v.z); p[3] = f2tf(v.w);
    }
    #pragma unroll
    for (int i = tid; i < 4096; i += 256) {      // x tile: 128 rows x 32 float4
        int r = i >> 5, q = i & 31;
        int gr = row0 + r;
        float4 v = (gr < NN) ? x4[gr * 32 + q] : make_float4(0, 0, 0, 0);
        unsigned* p = &xs[r * 132 + q * 4];
        p[0] = f2tf(v.x); p[1] = f2tf(v.y); p[2] = f2tf(v.z); p[3] = f2tf(v.w);
    }
    __syncthreads();

    int warp = tid >> 5, lane = tid & 31;
    int gid = lane >> 2, tig = lane & 3;
    int wr = warp * 16;                           // warp's row base in tile
    float acc[8][4];
    #pragma unroll
    for (int nt = 0; nt < 8; nt++)
        #pragma unroll
        for (int j = 0; j < 4; j++) acc[nt][j] = 0.f;

    #pragma unroll 4
    for (int ks = 0; ks < 16; ks++) {
        int k0 = ks * 8;
        unsigned a[4];
        a[0] = xs[(wr + gid) * 132 + k0 + tig];
        a[1] = xs[(wr + gid + 8) * 132 + k0 + tig];
        a[2] = xs[(wr + gid) * 132 + k0 + tig + 4];
        a[3] = xs[(wr + gid + 8) * 132 + k0 + tig + 4];
        #pragma unroll
        for (int nt = 0; nt < 8; nt++) {
            unsigned b0 = ws[(k0 + tig) * 72 + nt * 8 + gid];
            unsigned b1 = ws[(k0 + tig + 4) * 72 + nt * 8 + gid];
            mma_tf32(acc[nt], a, b0, b1);
        }
    }

    int r0 = row0 + wr + gid;
    int r1 = r0 + 8;
    float s0 = (r0 < NN) ? g_dinv[r0] : 0.f;
    float s1 = (r1 < NN) ? g_dinv[r1] : 0.f;
    float2* t2 = (float2*)g_t;
    #pragma unroll
    for (int nt = 0; nt < 8; nt++) {
        int c2i = nt * 4 + tig;                   // float2 index of col nt*8+2*tig
        if (r0 < NN) t2[r0 * 32 + c2i] = make_float2(s0 * acc[nt][0], s0 * acc[nt][1]);
        if (r1 < NN) t2[r1 * 32 + c2i] = make_float2(s1 * acc[nt][2], s1 * acc[nt][3]);
    }
}

// CSR gather-reduce: a[d] = tt[d] + sum_{s in nbrs(d)} tt[s]. No atomics.
__global__ __launch_bounds__(256) void k_aggcsr() {
    int idx = blockIdx.x * 256 + threadIdx.x;
    int d = idx >> 4;
    if (d >= NN) return;
    int sub = idx & 15;
    const float4* t4 = (const float4*)g_t;
    int beg = g_off[d], end = g_off[d + 1];
    float4 acc0 = t4[d * 16 + sub];   // self-loop term
    float4 acc1 = {0, 0, 0, 0};
    int j = beg;
    for (; j + 1 < end; j += 2) {
        int s0 = g_srcs[j];
        int s1 = g_srcs[j + 1];
        float4 v0 = t4[s0 * 16 + sub];
        float4 v1 = t4[s1 * 16 + sub];
        acc0.x += v0.x; acc0.y += v0.y; acc0.z += v0.z; acc0.w += v0.w;
        acc1.x += v1.x; acc1.y += v1.y; acc1.z += v1.z; acc1.w += v1.w;
    }
    if (j < end) {
        int s0 = g_srcs[j];
        float4 v0 = t4[s0 * 16 + sub];
        acc0.x += v0.x; acc0.y += v0.y; acc0.z += v0.z; acc0.w += v0.w;
    }
    acc0.x += acc1.x; acc0.y += acc1.y; acc0.z += acc1.z; acc0.w += acc1.w;
    ((float4*)g_a)[d * 16 + sub] = acc0;
}

// h = relu(dinv*a + b1); store hh = dinv*h into g_t.
__global__ void k_relu(const float* __restrict__ b1) {
    int i = blockIdx.x * 256 + threadIdx.x;
    if (i >= NN * 16) return;
    int node = i >> 4, c4 = i & 15;
    float s = g_dinv[node];
    float4 v = ((float4*)g_a)[i];
    float4 b = ((const float4*)b1)[c4];
    v.x = fmaxf(s * v.x + b.x, 0.f) * s;
    v.y = fmaxf(s * v.y + b.y, 0.f) * s;
    v.z = fmaxf(s * v.z + b.z, 0.f) * s;
    v.w = fmaxf(s * v.w + b.w, 0.f) * s;
    ((float4*)g_t)[i] = v;
}

// out = (dinv*a)[N,64] @ W2[64,128] + b2 via tf32 mma. 128 rows/block.
__global__ __launch_bounds__(256) void k_gemm2(const float* __restrict__ W2,
                                               const float* __restrict__ b2,
                                               float* __restrict__ out) {
    __shared__ unsigned xs[128 * 68];    // (dinv*a) tile, tf32, [row][k] pad 68
    __shared__ unsigned ws[64 * 136];    // W2, tf32, [k][n] pad 136
    int tid = threadIdx.x;
    int row0 = blockIdx.x * 128;
    const float4* a4 = (const float4*)g_a;
    const float4* W4 = (const float4*)W2;

    #pragma unroll
    for (int i = tid; i < 2048; i += 256) {      // W2: 64x128 = 2048 float4
        int k = i >> 5, q = i & 31;
        float4 v = W4[i];
        unsigned* p = &ws[k * 136 + q * 4];
        p[0] = f2tf(v.x); p[1] = f2tf(v.y); p[2] = f2tf(v.z); p[3] = f2tf(v.w);
    }
    #pragma unroll
    for (int i = tid; i < 2048; i += 256) {      // a tile: 128 rows x 16 float4
        int r = i >> 4, q = i & 15;
        int gr = row0 + r;
        float4 v = make_float4(0, 0, 0, 0);
        float s = 0.f;
        if (gr < NN) { v = a4[gr * 16 + q]; s = g_dinv[gr]; }
        unsigned* p = &xs[r * 68 + q * 4];
        p[0] = f2tf(s * v.x); p[1] = f2tf(s * v.y);
        p[2] = f2tf(s * v.z); p[3] = f2tf(s * v.w);
    }
    __syncthreads();

    int warp = tid >> 5, lane = tid & 31;
    int gid = lane >> 2, tig = lane & 3;
    int wr = warp * 16;
    float acc[16][4];
    #pragma unroll
    for (int nt = 0; nt < 16; nt++)
        #pragma unroll
        for (int j = 0; j < 4; j++) acc[nt][j] = 0.f;

    #pragma unroll 2
    for (int ks = 0; ks < 8; ks++) {
        int k0 = ks * 8;
        unsigned a[4];
        a[0] = xs[(wr + gid) * 68 + k0 + tig];
        a[1] = xs[(wr + gid + 8) * 68 + k0 + tig];
        a[2] = xs[(wr + gid) * 68 + k0 + tig + 4];
        a[3] = xs[(wr + gid + 8) * 68 + k0 + tig + 4];
        #pragma unroll
        for (int nt = 0; nt < 16; nt++) {
            unsigned b0 = ws[(k0 + tig) * 136 + nt * 8 + gid];
            unsigned b1 = ws[(k0 + tig + 4) * 136 + nt * 8 + gid];
            mma_tf32(acc[nt], a, b0, b1);
        }
    }

    int r0 = row0 + wr + gid;
    int r1 = r0 + 8;
    float2* o2 = (float2*)out;
    #pragma unroll
    for (int nt = 0; nt < 16; nt++) {
        int col = nt * 8 + 2 * tig;
        float bx = __ldg(&b2[col]), by = __ldg(&b2[col + 1]);
        int c2i = col >> 1;
        if (r0 < NN) o2[r0 * 64 + c2i] = make_float2(acc[nt][0] + bx, acc[nt][1] + by);
        if (r1 < NN) o2[r1 * 64 + c2i] = make_float2(acc[nt][2] + bx, acc[nt][3] + by);
    }
}

extern "C" void kernel_launch(void* const* d_in, const int* in_sizes, int n_in,
                              void* d_out, int out_size) {
    const float* x  = (const float*)d_in[0];
    const int*   ei = (const int*)d_in[1];   // [2, E] int32
    const float* W1 = (const float*)d_in[2];
    const float* b1 = (const float*)d_in[3];
    const float* W2 = (const float*)d_in[4];
    const float* b2 = (const float*)d_in[5];
    float* out = (float*)d_out;

    const int* src = ei;
    const int* dst = ei + NE;

    // CSR build
    k_zero   <<<(NN + 255) / 256, 256>>>();
    k_count  <<<(NE + 255) / 256, 256>>>(dst);
    k_scan1  <<<NB_SCAN, 256>>>();
    k_scan2  <<<1, 32>>>();
    k_scan3  <<<(NN + 255) / 256, 256>>>();
    k_fillcsr<<<(NE + 255) / 256, 256>>>(src, dst);
    // GCN layers
    k_gemm1  <<<(NN + 127) / 128, 256>>>(x, W1);
    k_aggcsr <<<(NN * 16 + 255) / 256, 256>>>();
    k_relu   <<<(NN * 16) / 256, 256>>>(b1);
    k_aggcsr <<<(NN * 16 + 255) / 256, 256>>>();
    k_gemm2  <<<(NN + 127) / 128, 256>>>(W2, b2, out);
}